// round 14
// baseline (speedup 1.0000x reference)
#include <cuda_runtime.h>
#include <math.h>

#define N_NODES  50000
#define N_EDGES  400000
#define NCH      16
#define MAX_DEG  64
#define TOTAL_NK (N_NODES * NCH)            // 800000
#define OUT1_OFF (N_NODES * NCH)            // 800000
#define OUT2_OFF (N_NODES * NCH * 4)        // 3200000
#define WPB      8                          // warps (=nodes) per block
#define NCOMP    13                         // s, v(3), M(9)
#define PI10     0.3141592653589793f        // pi/Rcut
#define CRBF     0.44721359549995794f       // sqrt(2/Rcut)

#define GEOM_T       100000                 // threads; each does 4 edges
#define GEOM_BLOCKS  391                    // ceil(100000/256)
#define PACK_BLOCKS  3125                   // 800000/256

typedef unsigned long long F2;

__device__ __forceinline__ F2 f2pack(float lo, float hi) {
    F2 r; asm("mov.b64 %0,{%1,%2};" : "=l"(r) : "f"(lo), "f"(hi)); return r;
}
__device__ __forceinline__ void f2unpack(F2 v, float& lo, float& hi) {
    asm("mov.b64 {%0,%1},%2;" : "=f"(lo), "=f"(hi) : "l"(v));
}
__device__ __forceinline__ F2 f2fma(F2 a, F2 b, F2 c) {
    F2 d; asm("fma.rn.f32x2 %0,%1,%2,%3;" : "=l"(d) : "l"(a), "l"(b), "l"(c)); return d;
}
__device__ __forceinline__ F2 f2add(F2 a, F2 b) {
    F2 d; asm("add.rn.f32x2 %0,%1,%2;" : "=l"(d) : "l"(a), "l"(b)); return d;
}
__device__ __forceinline__ F2 f2mul(F2 a, F2 b) {
    F2 d; asm("mul.rn.f32x2 %0,%1,%2;" : "=l"(d) : "l"(a), "l"(b)); return d;
}

// ---- scratch (__device__ globals: no allocation allowed) ----
__device__ float  g_dist[N_EDGES];
__device__ int    g_cnt[N_NODES];                 // degree by src (zero at entry, reset by gather)
__device__ float4 g_rec4[N_NODES * MAX_DEG];      // (ux,uy,uz, dst-as-bits) bucketed by src
__device__ int    g_rece[N_NODES * MAX_DEG];      // original edge id per slot
__device__ float  g_hp[N_NODES * NCOMP * NCH];    // h transposed: [n][component][k]

// fused prep: geom blocks (4 edges/thread, MLP=4) + h-transpose blocks
__global__ void prep_kernel(const float* __restrict__ pos,
                            const int* __restrict__ ei,
                            const float* __restrict__ h0,
                            const float* __restrict__ h1,
                            const float* __restrict__ h2) {
    if (blockIdx.x < GEOM_BLOCKS) {
        int t = blockIdx.x * blockDim.x + threadIdx.x;
        if (t >= GEOM_T) return;
        #pragma unroll
        for (int i = 0; i < 4; ++i) {
            int e = t + i * GEOM_T;                        // 4*100000 == N_EDGES
            int s = ei[e];
            int d = ei[N_EDGES + e];
            float rx = pos[3 * s + 0] - pos[3 * d + 0];
            float ry = pos[3 * s + 1] - pos[3 * d + 1];
            float rz = pos[3 * s + 2] - pos[3 * d + 2];
            float d2 = rx * rx + ry * ry + rz * rz;
            float inv = rsqrtf(d2);
            g_dist[e] = d2 * inv;
            int rank = atomicAdd(&g_cnt[s], 1);
            int slot = s * MAX_DEG + rank;
            g_rec4[slot] = make_float4(rx * inv, ry * inv, rz * inv, __int_as_float(d));
            g_rece[slot] = e;
        }
    } else {
        int idx = (blockIdx.x - GEOM_BLOCKS) * blockDim.x + threadIdx.x;
        if (idx >= TOTAL_NK) return;
        int n = idx >> 4;
        int k = idx & 15;
        float* o = g_hp + (n * NCOMP) * NCH + k;
        o[0] = h0[idx];
        const float* vp = h1 + (size_t)idx * 3;
        o[1 * NCH] = vp[0];
        o[2 * NCH] = vp[1];
        o[3 * NCH] = vp[2];
        const float* Mp = h2 + (size_t)idx * 9;
        #pragma unroll
        for (int c = 0; c < 9; ++c) o[(4 + c) * NCH] = Mp[c];
    }
}

// gather: ONE WARP PER NODE. Half-warp h handles edge PAIR (4j+2h, 4j+2h+1);
// lanes k=0..15 are channels. Pair packed into f32x2 -> math covers 4 edges
// per warp-iteration with R12's proven scalar-LDG coalescing.
__global__ void __launch_bounds__(256, 4)
gather_kernel(float* __restrict__ out) {
    __shared__ float4 sh[WPB * 52];        // epilogue staging only

    int warpid = threadIdx.x >> 5;
    int lane   = threadIdx.x & 31;
    int half   = lane >> 4;
    int k      = lane & 15;
    int n      = blockIdx.x * WPB + warpid;

    int cnt = g_cnt[n];
    int off = n * MAX_DEG;

    const F2 TWO = 0x4000000040000000ULL;  // (2.0f, 2.0f)

    F2 A0 = 0, A1x = 0, A1y = 0, A1z = 0;
    F2 A2[9] = {0,0,0,0,0,0,0,0,0};

    int jmax = (cnt + 3) >> 2;
    for (int j = 0; j < jmax; ++j) {
        int pe = 4 * j + 2 * half;
        bool vA = pe < cnt;
        bool vB = pe + 1 < cnt;
        int slotA = off + (vA ? pe : 0);
        int slotB = off + (vB ? pe + 1 : 0);

        float4 recA = __ldg(&g_rec4[slotA]);   // broadcast within half-warp
        float4 recB = __ldg(&g_rec4[slotB]);
        int    eA   = __ldg(&g_rece[slotA]);
        int    eB   = __ldg(&g_rece[slotB]);
        int dstA = __float_as_int(recA.w);
        int dstB = __float_as_int(recB.w);

        // R12-style scalar loads: each instr = 2 rows x 64B (2 lines/warp)
        const float* hpA = g_hp + (size_t)dstA * (NCOMP * NCH) + k;
        const float* hpB = g_hp + (size_t)dstB * (NCOMP * NCH) + k;
        float sA   = __ldg(hpA +  0 * NCH), sB   = __ldg(hpB +  0 * NCH);
        float vxA  = __ldg(hpA +  1 * NCH), vxB  = __ldg(hpB +  1 * NCH);
        float vyA  = __ldg(hpA +  2 * NCH), vyB  = __ldg(hpB +  2 * NCH);
        float vzA  = __ldg(hpA +  3 * NCH), vzB  = __ldg(hpB +  3 * NCH);
        float m00A = __ldg(hpA +  4 * NCH), m00B = __ldg(hpB +  4 * NCH);
        float m01A = __ldg(hpA +  5 * NCH), m01B = __ldg(hpB +  5 * NCH);
        float m02A = __ldg(hpA +  6 * NCH), m02B = __ldg(hpB +  6 * NCH);
        float m10A = __ldg(hpA +  7 * NCH), m10B = __ldg(hpB +  7 * NCH);
        float m11A = __ldg(hpA +  8 * NCH), m11B = __ldg(hpB +  8 * NCH);
        float m12A = __ldg(hpA +  9 * NCH), m12B = __ldg(hpB +  9 * NCH);
        float m20A = __ldg(hpA + 10 * NCH), m20B = __ldg(hpB + 10 * NCH);
        float m21A = __ldg(hpA + 11 * NCH), m21B = __ldg(hpB + 11 * NCH);
        float m22A = __ldg(hpA + 12 * NCH), m22B = __ldg(hpB + 12 * NCH);

        // inline radial per edge (faithful [K,E]->[E,K] reshape quirk)
        unsigned fA = (unsigned)eA * 16u + (unsigned)k;
        unsigned nA = fA / N_EDGES, eiA = fA - nA * N_EDGES;
        unsigned fB = (unsigned)eB * 16u + (unsigned)k;
        unsigned nB = fB / N_EDGES, eiB = fB - nB * N_EDGES;
        float rrA = __ldg(g_dist + eiA);
        float rrB = __ldg(g_dist + eiB);
        float rhoA = vA ? (CRBF * __sinf((float)(nA + 1) * PI10 * rrA) / rrA) : 0.0f;
        float rhoB = vB ? (CRBF * __sinf((float)(nB + 1) * PI10 * rrB) / rrB) : 0.0f;

        F2 RHO = f2pack(rhoA, rhoB);
        F2 UX  = f2pack(recA.x, recB.x);
        F2 UY  = f2pack(recA.y, recB.y);
        F2 UZ  = f2pack(recA.z, recB.z);

        F2 S   = f2pack(sA,   sB);
        F2 VX  = f2pack(vxA,  vxB);
        F2 VY  = f2pack(vyA,  vyB);
        F2 VZ  = f2pack(vzA,  vzB);
        F2 M00 = f2pack(m00A, m00B);
        F2 M01 = f2pack(m01A, m01B);
        F2 M02 = f2pack(m02A, m02B);
        F2 M10 = f2pack(m10A, m10B);
        F2 M11 = f2pack(m11A, m11B);
        F2 M12 = f2pack(m12A, m12B);
        F2 M20 = f2pack(m20A, m20B);
        F2 M21 = f2pack(m21A, m21B);
        F2 M22 = f2pack(m22A, m22B);

        F2 vd  = f2fma(VX, UX, f2fma(VY, UY, f2mul(VZ, UZ)));
        F2 tr  = f2add(M00, f2add(M11, M22));
        F2 Mux = f2fma(M00, UX, f2fma(M01, UY, f2mul(M02, UZ)));
        F2 Muy = f2fma(M10, UX, f2fma(M11, UY, f2mul(M12, UZ)));
        F2 Muz = f2fma(M20, UX, f2fma(M21, UY, f2mul(M22, UZ)));
        F2 Mtux = f2fma(M00, UX, f2fma(M10, UY, f2mul(M20, UZ)));
        F2 Mtuy = f2fma(M01, UX, f2fma(M11, UY, f2mul(M21, UZ)));
        F2 Mtuz = f2fma(M02, UX, f2fma(M12, UY, f2mul(M22, UZ)));
        F2 uMu = f2fma(UX, Mux, f2fma(UY, Muy, f2mul(UZ, Muz)));

        // out0 += rho*(2s + vd + 2(tr + uMu))
        F2 t0 = f2fma(TWO, S, vd);
        t0 = f2fma(TWO, f2add(tr, uMu), t0);
        A0 = f2fma(RHO, t0, A0);

        F2 str = f2add(S, tr);
        F2 c1  = f2mul(RHO, f2fma(TWO, vd, str));
        F2 ct  = f2mul(RHO, str);

        F2 mx = f2add(Mux, Mtux);
        F2 my = f2add(Muy, Mtuy);
        F2 mz = f2add(Muz, Mtuz);

        // out1_c += c1*u_c + rho*(2v_c + m_c)
        A1x = f2fma(c1, UX, f2fma(RHO, f2fma(TWO, VX, mx), A1x));
        A1y = f2fma(c1, UY, f2fma(RHO, f2fma(TWO, VY, my), A1y));
        A1z = f2fma(c1, UZ, f2fma(RHO, f2fma(TWO, VZ, mz), A1z));

        // a_c = ct*u_c + rho*(v_c + 2*m_c);  out2_ij += 2rho*M_ij + a_i u_j
        F2 ax = f2fma(ct, UX, f2mul(RHO, f2fma(TWO, mx, VX)));
        F2 ay = f2fma(ct, UY, f2mul(RHO, f2fma(TWO, my, VY)));
        F2 az = f2fma(ct, UZ, f2mul(RHO, f2fma(TWO, mz, VZ)));
        F2 r2m = f2mul(TWO, RHO);
        A2[0] = f2fma(r2m, M00, f2fma(ax, UX, A2[0]));
        A2[1] = f2fma(r2m, M01, f2fma(ax, UY, A2[1]));
        A2[2] = f2fma(r2m, M02, f2fma(ax, UZ, A2[2]));
        A2[3] = f2fma(r2m, M10, f2fma(ay, UX, A2[3]));
        A2[4] = f2fma(r2m, M11, f2fma(ay, UY, A2[4]));
        A2[5] = f2fma(r2m, M12, f2fma(ay, UZ, A2[5]));
        A2[6] = f2fma(r2m, M20, f2fma(az, UX, A2[6]));
        A2[7] = f2fma(r2m, M21, f2fma(az, UY, A2[7]));
        A2[8] = f2fma(r2m, M22, f2fma(az, UZ, A2[8]));
    }

    // fold the pair (lo=edge A, hi=edge B), then merge the two half-warps
    const unsigned FULL = 0xffffffffu;
    float a0, a1x, a1y, a1z, a2[9];
    { float lo, hi;
      f2unpack(A0,  lo, hi); a0  = lo + hi;
      f2unpack(A1x, lo, hi); a1x = lo + hi;
      f2unpack(A1y, lo, hi); a1y = lo + hi;
      f2unpack(A1z, lo, hi); a1z = lo + hi;
      #pragma unroll
      for (int c = 0; c < 9; ++c) { f2unpack(A2[c], lo, hi); a2[c] = lo + hi; }
    }
    a0  += __shfl_xor_sync(FULL, a0, 16);
    a1x += __shfl_xor_sync(FULL, a1x, 16);
    a1y += __shfl_xor_sync(FULL, a1y, 16);
    a1z += __shfl_xor_sync(FULL, a1z, 16);
    #pragma unroll
    for (int c = 0; c < 9; ++c) a2[c] += __shfl_xor_sync(FULL, a2[c], 16);

    // staged output: per-channel layout in smem, then coalesced f4 stores
    float* w = (float*)(sh + warpid * 52);
    if (half == 0) {
        w[k] = a0;
        w[16 + 3 * k] = a1x; w[17 + 3 * k] = a1y; w[18 + 3 * k] = a1z;
        float* mw = w + 64 + 9 * k;
        #pragma unroll
        for (int c = 0; c < 9; ++c) mw[c] = a2[c];
    }
    __syncwarp();

    const float4* rd = sh + warpid * 52;      // 52 f4 = {out0row, out1row, out2row}
    float4* O0 = (float4*)(out + (size_t)n * 16);
    float4* O1 = (float4*)(out + OUT1_OFF + (size_t)n * 48);
    float4* O2 = (float4*)(out + OUT2_OFF + (size_t)n * 144);
    {
        float4 val = rd[lane];
        float4* p = (lane < 4) ? (O0 + lane)
                  : ((lane < 16) ? (O1 + lane - 4) : (O2 + lane - 16));
        *p = val;
    }
    {
        int t = lane + 32;                     // 32..51
        if (t < 52) O2[t - 16] = rd[t];
    }

    if (lane == 0) g_cnt[n] = 0;               // reset for next launch
}

extern "C" void kernel_launch(void* const* d_in, const int* in_sizes, int n_in,
                              void* d_out, int out_size) {
    const float* h0  = (const float*)d_in[0];
    const float* h1  = (const float*)d_in[1];
    const float* h2  = (const float*)d_in[2];
    const float* pos = (const float*)d_in[3];
    // d_in[4] = channel_weights (provably unused by reference output)
    const int*   ei  = (const int*)d_in[5];
    float* out = (float*)d_out;

    prep_kernel<<<GEOM_BLOCKS + PACK_BLOCKS, 256>>>(pos, ei, h0, h1, h2);
    gather_kernel<<<N_NODES / WPB, 32 * WPB>>>(out);
}

// round 15
// speedup vs baseline: 1.6643x; 1.6643x over previous
#include <cuda_runtime.h>
#include <math.h>

#define N_NODES  50000
#define N_EDGES  400000
#define NCH      16
#define MAX_DEG  64
#define TOTAL_NK (N_NODES * NCH)            // 800000
#define OUT1_OFF (N_NODES * NCH)            // 800000
#define OUT2_OFF (N_NODES * NCH * 4)        // 3200000
#define WPB      8                          // warps per block
#define NPW      8                          // nodes per warp (sequential)
#define NCOMP    13                         // s, v(3), M(9)
#define PI10     0.3141592653589793f        // pi/Rcut
#define CRBF     0.44721359549995794f       // sqrt(2/Rcut)

#define GEOM_T       100000                 // threads; each does 4 edges
#define GEOM_BLOCKS  391                    // ceil(100000/256)
#define PACK_BLOCKS  3125                   // 800000/256

// ---- scratch (__device__ globals: no allocation allowed) ----
__device__ float  g_dist[N_EDGES];
__device__ int    g_cnt[N_NODES];                 // degree by src (zero at entry, reset by gather)
__device__ float4 g_rec4[N_NODES * MAX_DEG];      // (ux,uy,uz, dst-as-bits) bucketed by src
__device__ int    g_rece[N_NODES * MAX_DEG];      // original edge id per slot
__device__ float  g_hp[N_NODES * NCOMP * NCH];    // h transposed: [n][component][k]

// fused prep: geom blocks (4 edges/thread, MLP=4) + h-transpose blocks
__global__ void prep_kernel(const float* __restrict__ pos,
                            const int* __restrict__ ei,
                            const float* __restrict__ h0,
                            const float* __restrict__ h1,
                            const float* __restrict__ h2) {
    if (blockIdx.x < GEOM_BLOCKS) {
        int t = blockIdx.x * blockDim.x + threadIdx.x;
        if (t >= GEOM_T) return;
        #pragma unroll
        for (int i = 0; i < 4; ++i) {
            int e = t + i * GEOM_T;                        // 4*100000 == N_EDGES
            int s = ei[e];
            int d = ei[N_EDGES + e];
            float rx = pos[3 * s + 0] - pos[3 * d + 0];
            float ry = pos[3 * s + 1] - pos[3 * d + 1];
            float rz = pos[3 * s + 2] - pos[3 * d + 2];
            float d2 = rx * rx + ry * ry + rz * rz;
            float inv = rsqrtf(d2);
            g_dist[e] = d2 * inv;
            int rank = atomicAdd(&g_cnt[s], 1);
            int slot = s * MAX_DEG + rank;
            g_rec4[slot] = make_float4(rx * inv, ry * inv, rz * inv, __int_as_float(d));
            g_rece[slot] = e;
        }
    } else {
        int idx = (blockIdx.x - GEOM_BLOCKS) * blockDim.x + threadIdx.x;
        if (idx >= TOTAL_NK) return;
        int n = idx >> 4;
        int k = idx & 15;
        float* o = g_hp + (n * NCOMP) * NCH + k;
        o[0] = h0[idx];
        const float* vp = h1 + (size_t)idx * 3;
        o[1 * NCH] = vp[0];
        o[2 * NCH] = vp[1];
        o[3 * NCH] = vp[2];
        const float* Mp = h2 + (size_t)idx * 9;
        #pragma unroll
        for (int c = 0; c < 9; ++c) o[(4 + c) * NCH] = Mp[c];
    }
}

// gather: each warp processes NPW consecutive nodes sequentially (work
// averaging kills per-block degree-imbalance). Half-warp h handles edges
// 2j+h of the current node; lanes k=0..15 are channels. R12 loop body.
__global__ void __launch_bounds__(256, 5)
gather_kernel(float* __restrict__ out) {
    __shared__ float4 sh[WPB * 52];        // epilogue staging only

    int warpid = threadIdx.x >> 5;
    int lane   = threadIdx.x & 31;
    int half   = lane >> 4;
    int k      = lane & 15;
    int nbase  = (blockIdx.x * WPB + warpid) * NPW;

    for (int i = 0; i < NPW; ++i) {
        int n = nbase + i;
        if (n >= N_NODES) break;

        int cnt = g_cnt[n];
        int off = n * MAX_DEG;

        float a0 = 0.0f;
        float a1x = 0.0f, a1y = 0.0f, a1z = 0.0f;
        float a2[9] = {0,0,0,0,0,0,0,0,0};

        int jmax = (cnt + 1) >> 1;
        for (int j = 0; j < jmax; ++j) {
            int idx2 = 2 * j + half;
            bool valid = idx2 < cnt;
            int slot = off + (valid ? idx2 : 0);

            float4 rec = __ldg(&g_rec4[slot]);     // broadcast within half-warp
            int    e   = __ldg(&g_rece[slot]);
            int dst = __float_as_int(rec.w);
            float ux = rec.x, uy = rec.y, uz = rec.z;

            // packed h row: 13 LDGs, all independent, issued back-to-back
            const float* hp = g_hp + (size_t)(dst * NCOMP) * NCH + k;
            float s   = __ldg(hp);
            float vx  = __ldg(hp + 1 * NCH),  vy  = __ldg(hp + 2 * NCH),  vz  = __ldg(hp + 3 * NCH);
            float M00 = __ldg(hp + 4 * NCH),  M01 = __ldg(hp + 5 * NCH),  M02 = __ldg(hp + 6 * NCH);
            float M10 = __ldg(hp + 7 * NCH),  M11 = __ldg(hp + 8 * NCH),  M12 = __ldg(hp + 9 * NCH);
            float M20 = __ldg(hp + 10 * NCH), M21 = __ldg(hp + 11 * NCH), M22 = __ldg(hp + 12 * NCH);

            // inline radial (faithful [K,E]->[E,K] reshape quirk)
            unsigned flat  = (unsigned)e * 16u + (unsigned)k;
            unsigned n_idx = flat / N_EDGES;
            unsigned e_idx = flat - n_idx * N_EDGES;
            float rr  = __ldg(g_dist + e_idx);
            float rho = valid ? (CRBF * __sinf((float)(n_idx + 1) * PI10 * rr) / rr) : 0.0f;

            float vd = vx * ux + vy * uy + vz * uz;
            float tr = M00 + M11 + M22;
            float Mux  = M00 * ux + M01 * uy + M02 * uz;
            float Muy  = M10 * ux + M11 * uy + M12 * uz;
            float Muz  = M20 * ux + M21 * uy + M22 * uz;
            float Mtux = M00 * ux + M10 * uy + M20 * uz;
            float Mtuy = M01 * ux + M11 * uy + M21 * uz;
            float Mtuz = M02 * ux + M12 * uy + M22 * uz;
            float uMu  = ux * Mux + uy * Muy + uz * Muz;

            a0 += rho * (2.0f * s + vd + 2.0f * tr + 2.0f * uMu);

            float c1 = rho * (s + 2.0f * vd + tr);
            a1x += c1 * ux + rho * (2.0f * vx + Mux + Mtux);
            a1y += c1 * uy + rho * (2.0f * vy + Muy + Mtuy);
            a1z += c1 * uz + rho * (2.0f * vz + Muz + Mtuz);

            float ct = rho * (s + tr);
            float ax = ct * ux + rho * (vx + 2.0f * (Mux + Mtux));
            float ay = ct * uy + rho * (vy + 2.0f * (Muy + Mtuy));
            float az = ct * uz + rho * (vz + 2.0f * (Muz + Mtuz));
            float r2m = 2.0f * rho;
            a2[0] += r2m * M00 + ax * ux;
            a2[1] += r2m * M01 + ax * uy;
            a2[2] += r2m * M02 + ax * uz;
            a2[3] += r2m * M10 + ay * ux;
            a2[4] += r2m * M11 + ay * uy;
            a2[5] += r2m * M12 + ay * uz;
            a2[6] += r2m * M20 + az * ux;
            a2[7] += r2m * M21 + az * uy;
            a2[8] += r2m * M22 + az * uz;
        }

        // merge the two half-warps (same channels, disjoint edges)
        const unsigned FULL = 0xffffffffu;
        a0  += __shfl_xor_sync(FULL, a0, 16);
        a1x += __shfl_xor_sync(FULL, a1x, 16);
        a1y += __shfl_xor_sync(FULL, a1y, 16);
        a1z += __shfl_xor_sync(FULL, a1z, 16);
        #pragma unroll
        for (int c = 0; c < 9; ++c) a2[c] += __shfl_xor_sync(FULL, a2[c], 16);

        // staged output: per-channel layout in smem, then coalesced f4 stores
        float* w = (float*)(sh + warpid * 52);
        if (half == 0) {
            w[k] = a0;
            w[16 + 3 * k] = a1x; w[17 + 3 * k] = a1y; w[18 + 3 * k] = a1z;
            float* mw = w + 64 + 9 * k;
            #pragma unroll
            for (int c = 0; c < 9; ++c) mw[c] = a2[c];
        }
        __syncwarp();

        const float4* rd = sh + warpid * 52;  // 52 f4 = {out0row, out1row, out2row}
        float4* O0 = (float4*)(out + (size_t)n * 16);
        float4* O1 = (float4*)(out + OUT1_OFF + (size_t)n * 48);
        float4* O2 = (float4*)(out + OUT2_OFF + (size_t)n * 144);
        {
            float4 val = rd[lane];
            float4* p = (lane < 4) ? (O0 + lane)
                      : ((lane < 16) ? (O1 + lane - 4) : (O2 + lane - 16));
            *p = val;
        }
        {
            int t = lane + 32;                 // 32..51
            if (t < 52) O2[t - 16] = rd[t];
        }

        if (lane == 0) g_cnt[n] = 0;           // reset for next launch
        __syncwarp();                          // staging reusable for next node
    }
}

extern "C" void kernel_launch(void* const* d_in, const int* in_sizes, int n_in,
                              void* d_out, int out_size) {
    const float* h0  = (const float*)d_in[0];
    const float* h1  = (const float*)d_in[1];
    const float* h2  = (const float*)d_in[2];
    const float* pos = (const float*)d_in[3];
    // d_in[4] = channel_weights (provably unused by reference output)
    const int*   ei  = (const int*)d_in[5];
    float* out = (float*)d_out;

    prep_kernel<<<GEOM_BLOCKS + PACK_BLOCKS, 256>>>(pos, ei, h0, h1, h2);
    int gblocks = (N_NODES + WPB * NPW - 1) / (WPB * NPW);   // 782
    gather_kernel<<<gblocks, 32 * WPB>>>(out);
}

// round 16
// speedup vs baseline: 2.0302x; 1.2198x over previous
#include <cuda_runtime.h>
#include <math.h>

#define N_NODES  50000
#define N_EDGES  400000
#define NCH      16
#define MAX_DEG  64
#define TOTAL_NK (N_NODES * NCH)            // 800000
#define OUT1_OFF (N_NODES * NCH)            // 800000
#define OUT2_OFF (N_NODES * NCH * 4)        // 3200000
#define WPB      8                          // warps per block
#define NCOMP    13                         // s, v(3), M(9)
#define PI10     0.3141592653589793f        // pi/Rcut
#define CRBF     0.44721359549995794f       // sqrt(2/Rcut)

#define GEOM_T       100000                 // threads; each does 4 edges
#define GEOM_BLOCKS  391                    // ceil(100000/256)
#define PACK_BLOCKS  3125                   // 50000 nodes / 16 per block

// ---- scratch (__device__ globals: no allocation allowed) ----
__device__ float  g_dist[N_EDGES];
__device__ int    g_cnt[N_NODES];                 // degree by src (zero at entry, reset by gather)
__device__ float4 g_rec4[N_NODES * MAX_DEG];      // (ux,uy,uz, dst-as-bits) bucketed by src
__device__ int    g_rece[N_NODES * MAX_DEG];      // original edge id per slot
__device__ float  g_hp[N_NODES * NCOMP * NCH];    // h transposed: [n][component][k]

// fused prep: geom blocks (4 edges/thread, MLP=4) + smem-transpose pack blocks
__global__ void prep_kernel(const float* __restrict__ pos,
                            const int* __restrict__ ei,
                            const float* __restrict__ h0,
                            const float* __restrict__ h1,
                            const float* __restrict__ h2) {
    __shared__ float sm[3072];             // 16 nodes: h1 (768 f) + h2 (2304 f)

    if (blockIdx.x < GEOM_BLOCKS) {
        int t = blockIdx.x * blockDim.x + threadIdx.x;
        if (t >= GEOM_T) return;
        #pragma unroll
        for (int i = 0; i < 4; ++i) {
            int e = t + i * GEOM_T;                        // 4*100000 == N_EDGES
            int s = ei[e];
            int d = ei[N_EDGES + e];
            float rx = pos[3 * s + 0] - pos[3 * d + 0];
            float ry = pos[3 * s + 1] - pos[3 * d + 1];
            float rz = pos[3 * s + 2] - pos[3 * d + 2];
            float d2 = rx * rx + ry * ry + rz * rz;
            float inv = rsqrtf(d2);
            g_dist[e] = d2 * inv;
            int rank = atomicAdd(&g_cnt[s], 1);
            int slot = s * MAX_DEG + rank;
            g_rec4[slot] = make_float4(rx * inv, ry * inv, rz * inv, __int_as_float(d));
            g_rece[slot] = e;
        }
    } else {
        // pack: 16 nodes per block, coalesced f4 stage -> smem -> transposed hp
        int p   = blockIdx.x - GEOM_BLOCKS;
        int nb0 = p * 16;
        int tid = threadIdx.x;

        const float4* H1 = (const float4*)(h1 + (size_t)nb0 * 48);   // 192 f4
        const float4* H2 = (const float4*)(h2 + (size_t)nb0 * 144);  // 576 f4
        float4* S = (float4*)sm;
        // h1 slab -> sm[0..768), h2 slab -> sm[768..3072)
        if (tid < 192) S[tid] = __ldg(H1 + tid);
        S[192 + tid] = __ldg(H2 + tid);
        S[448 + tid] = __ldg(H2 + 256 + tid);
        if (tid < 64) S[704 + tid] = __ldg(H2 + 512 + tid);
        __syncthreads();

        int nl = tid >> 4;                 // local node 0..15
        int k  = tid & 15;
        int idx = (nb0 + nl) * NCH + k;
        float* o = g_hp + (size_t)((nb0 + nl) * NCOMP) * NCH + k;

        o[0] = __ldg(h0 + idx);            // h0 direct (coalesced)
        const float* v = sm + nl * 48 + k * 3;          // stride 3: conflict-free
        o[1 * NCH] = v[0];
        o[2 * NCH] = v[1];
        o[3 * NCH] = v[2];
        const float* M = sm + 768 + nl * 144 + k * 9;   // stride 9: conflict-free
        #pragma unroll
        for (int c = 0; c < 9; ++c) o[(4 + c) * NCH] = M[c];
    }
}

// gather: ONE WARP PER NODE (R12 verbatim). Half-warp h handles edges 2j+h;
// lanes k=0..15 are channels. Packed h rows -> lane-contiguous LDGs.
__global__ void __launch_bounds__(256, 5)
gather_kernel(float* __restrict__ out) {
    __shared__ float4 sh[WPB * 52];        // epilogue staging only

    int warpid = threadIdx.x >> 5;
    int lane   = threadIdx.x & 31;
    int half   = lane >> 4;
    int k      = lane & 15;
    int n      = blockIdx.x * WPB + warpid;   // grid covers exactly N_NODES

    int cnt = g_cnt[n];
    int off = n * MAX_DEG;

    float a0 = 0.0f;
    float a1x = 0.0f, a1y = 0.0f, a1z = 0.0f;
    float a2[9] = {0,0,0,0,0,0,0,0,0};

    int jmax = (cnt + 1) >> 1;
    for (int j = 0; j < jmax; ++j) {
        int idx2 = 2 * j + half;
        bool valid = idx2 < cnt;
        int slot = off + (valid ? idx2 : 0);

        float4 rec = __ldg(&g_rec4[slot]);     // broadcast within half-warp
        int    e   = __ldg(&g_rece[slot]);
        int dst = __float_as_int(rec.w);
        float ux = rec.x, uy = rec.y, uz = rec.z;

        // packed h row: 13 LDGs, all independent, issued back-to-back
        const float* hp = g_hp + (size_t)(dst * NCOMP) * NCH + k;
        float s   = __ldg(hp);
        float vx  = __ldg(hp + 1 * NCH),  vy  = __ldg(hp + 2 * NCH),  vz  = __ldg(hp + 3 * NCH);
        float M00 = __ldg(hp + 4 * NCH),  M01 = __ldg(hp + 5 * NCH),  M02 = __ldg(hp + 6 * NCH);
        float M10 = __ldg(hp + 7 * NCH),  M11 = __ldg(hp + 8 * NCH),  M12 = __ldg(hp + 9 * NCH);
        float M20 = __ldg(hp + 10 * NCH), M21 = __ldg(hp + 11 * NCH), M22 = __ldg(hp + 12 * NCH);

        // inline radial (faithful [K,E]->[E,K] reshape quirk) overlaps the loads
        unsigned flat  = (unsigned)e * 16u + (unsigned)k;
        unsigned n_idx = flat / N_EDGES;
        unsigned e_idx = flat - n_idx * N_EDGES;
        float rr  = __ldg(g_dist + e_idx);
        float rho = valid ? (CRBF * __sinf((float)(n_idx + 1) * PI10 * rr) / rr) : 0.0f;

        float vd = vx * ux + vy * uy + vz * uz;
        float tr = M00 + M11 + M22;
        float Mux  = M00 * ux + M01 * uy + M02 * uz;
        float Muy  = M10 * ux + M11 * uy + M12 * uz;
        float Muz  = M20 * ux + M21 * uy + M22 * uz;
        float Mtux = M00 * ux + M10 * uy + M20 * uz;
        float Mtuy = M01 * ux + M11 * uy + M21 * uz;
        float Mtuz = M02 * ux + M12 * uy + M22 * uz;
        float uMu  = ux * Mux + uy * Muy + uz * Muz;

        a0 += rho * (2.0f * s + vd + 2.0f * tr + 2.0f * uMu);

        float c1 = rho * (s + 2.0f * vd + tr);
        a1x += c1 * ux + rho * (2.0f * vx + Mux + Mtux);
        a1y += c1 * uy + rho * (2.0f * vy + Muy + Mtuy);
        a1z += c1 * uz + rho * (2.0f * vz + Muz + Mtuz);

        float ct = rho * (s + tr);
        float ax = ct * ux + rho * (vx + 2.0f * (Mux + Mtux));
        float ay = ct * uy + rho * (vy + 2.0f * (Muy + Mtuy));
        float az = ct * uz + rho * (vz + 2.0f * (Muz + Mtuz));
        float r2m = 2.0f * rho;
        a2[0] += r2m * M00 + ax * ux;
        a2[1] += r2m * M01 + ax * uy;
        a2[2] += r2m * M02 + ax * uz;
        a2[3] += r2m * M10 + ay * ux;
        a2[4] += r2m * M11 + ay * uy;
        a2[5] += r2m * M12 + ay * uz;
        a2[6] += r2m * M20 + az * ux;
        a2[7] += r2m * M21 + az * uy;
        a2[8] += r2m * M22 + az * uz;
    }

    // merge the two half-warps (same channels, disjoint edges)
    const unsigned FULL = 0xffffffffu;
    a0  += __shfl_xor_sync(FULL, a0, 16);
    a1x += __shfl_xor_sync(FULL, a1x, 16);
    a1y += __shfl_xor_sync(FULL, a1y, 16);
    a1z += __shfl_xor_sync(FULL, a1z, 16);
    #pragma unroll
    for (int c = 0; c < 9; ++c) a2[c] += __shfl_xor_sync(FULL, a2[c], 16);

    // staged output: per-channel layout in smem, then coalesced f4 stores
    float* w = (float*)(sh + warpid * 52);
    if (half == 0) {
        w[k] = a0;
        w[16 + 3 * k] = a1x; w[17 + 3 * k] = a1y; w[18 + 3 * k] = a1z;
        float* mw = w + 64 + 9 * k;
        #pragma unroll
        for (int c = 0; c < 9; ++c) mw[c] = a2[c];
    }
    __syncwarp();

    const float4* rd = sh + warpid * 52;      // 52 f4 = {out0row, out1row, out2row}
    float4* O0 = (float4*)(out + (size_t)n * 16);
    float4* O1 = (float4*)(out + OUT1_OFF + (size_t)n * 48);
    float4* O2 = (float4*)(out + OUT2_OFF + (size_t)n * 144);
    {
        float4 val = rd[lane];
        float4* p = (lane < 4) ? (O0 + lane)
                  : ((lane < 16) ? (O1 + lane - 4) : (O2 + lane - 16));
        *p = val;
    }
    {
        int t = lane + 32;                     // 32..51
        if (t < 52) O2[t - 16] = rd[t];
    }

    if (lane == 0) g_cnt[n] = 0;               // reset for next launch
}

extern "C" void kernel_launch(void* const* d_in, const int* in_sizes, int n_in,
                              void* d_out, int out_size) {
    const float* h0  = (const float*)d_in[0];
    const float* h1  = (const float*)d_in[1];
    const float* h2  = (const float*)d_in[2];
    const float* pos = (const float*)d_in[3];
    // d_in[4] = channel_weights (provably unused by reference output)
    const int*   ei  = (const int*)d_in[5];
    float* out = (float*)d_out;

    prep_kernel<<<GEOM_BLOCKS + PACK_BLOCKS, 256>>>(pos, ei, h0, h1, h2);
    gather_kernel<<<N_NODES / WPB, 32 * WPB>>>(out);
}